// round 9
// baseline (speedup 1.0000x reference)
#include <cuda_runtime.h>
#include <cuda_fp16.h>
#include <cstdint>

// Problem dims
#define MDIM 8192   // B*S
#define NDIM 4096
#define KDIM 4096
#define K16  (KDIM / 16)     // 256 k16 tiles

// GEMM tiling: 128x128 CTA, 8 warps (4m x 2n), warp tile 32x64
#define TM 128
#define TN 128

// Pre-pass grid split (256-thread blocks, 8 warps each)
#define ACONV_BLOCKS ((MDIM / 16) * K16 / 8)        // 16384
#define DEQ_BLOCKS   ((NDIM / 64) * K16 / 8)        // 2048

// Fragment-layout scratch (allocation-free rule: __device__ globals)
// A: per (m16, k16) tile: 512B block, lane l owns bytes [16l, 16l+16) = a0..a3
__device__ uint4 g_Afrag[(MDIM / 16) * (size_t)K16 * 32];
// W: per (n64, k16) block: 2KB; j in 0..3 selects frag pair (2j, 2j+1);
// lane l owns bytes [j*512 + 16l, +16) = {f=2j: b0,b1, f=2j+1: b0,b1}
__device__ uint4 g_Wfrag[(NDIM / 64) * (size_t)K16 * 128];

// ---------------------------------------------------------------------------
__device__ __forceinline__ void mma16816(float* d, const uint32_t* a,
                                         const uint32_t* b) {
    asm volatile(
        "mma.sync.aligned.m16n8k16.row.col.f32.f16.f16.f32 "
        "{%0,%1,%2,%3}, {%4,%5,%6,%7}, {%8,%9}, {%0,%1,%2,%3};"
        : "+f"(d[0]), "+f"(d[1]), "+f"(d[2]), "+f"(d[3])
        : "r"(a[0]), "r"(a[1]), "r"(a[2]), "r"(a[3]), "r"(b[0]), "r"(b[1]));
}

__device__ __forceinline__ uint32_t pack_h2(float x, float y) {
    __half2 h = __floats2half2_rn(x, y);
    return *(uint32_t*)&h;
}

// ---------------------------------------------------------------------------
// Merged pre-pass.
// Blocks [0, ACONV_BLOCKS): A fp32 -> fp16 fragments.
//   Warp per (m16, k16). Lane l: a0=(m,k),a1=(m+8,k),a2=(m,k+8),a3=(m+8,k+8)
//   with m = l>>2, k = 2*(l&3) within tile. STG.128 at lane*16 (coalesced).
// Blocks [ACONV_BLOCKS, +DEQ_BLOCKS): GPTQ int4 dequant -> B fragments.
//   Warp per (n64, k16). Lane l handles frags f=0..7 (n = f*8 + l>>2),
//   reg0 = k 2(l&3)+{0,1}, reg1 = +8.
// ---------------------------------------------------------------------------
__global__ void __launch_bounds__(256)
k_pre(const float* __restrict__ in, const int* __restrict__ qw,
      const float* __restrict__ sc, const int* __restrict__ qz) {
    const int l = threadIdx.x & 31;
    if (blockIdx.x < ACONV_BLOCKS) {
        int w = (blockIdx.x << 3) | (threadIdx.x >> 5);
        int k16 = w & (K16 - 1);
        int m16 = w >> 8;
        int m = (m16 << 4) + (l >> 2);
        int k = (k16 << 4) + 2 * (l & 3);
        const float* p = in + (size_t)m * KDIM + k;
        float2 f0 = *(const float2*)(p);
        float2 f1 = *(const float2*)(p + 8 * KDIM);
        float2 f2 = *(const float2*)(p + 8);
        float2 f3 = *(const float2*)(p + 8 * KDIM + 8);
        uint4 o;
        o.x = pack_h2(f0.x, f0.y);
        o.y = pack_h2(f1.x, f1.y);
        o.z = pack_h2(f2.x, f2.y);
        o.w = pack_h2(f3.x, f3.y);
        g_Afrag[((size_t)m16 * K16 + k16) * 32 + l] = o;
    } else {
        int w = ((blockIdx.x - ACONV_BLOCKS) << 3) | (threadIdx.x >> 5);
        int k16 = w & (K16 - 1);
        int n64 = w >> 8;                 // 0..63
        int nb = n64 << 6;
        int g   = k16 >> 3;               // group = k/128
        int kk0 = k16 << 1;               // q row for k 0..7 of this tile
        int sh  = (l & 3) << 3;           // nibble-pair start bit
        uint4 ov[4];
#pragma unroll
        for (int j = 0; j < 4; ++j) {
            uint32_t r[4];
#pragma unroll
            for (int h = 0; h < 2; ++h) {
                int f = 2 * j + h;
                int n = nb + f * 8 + (l >> 2);
                uint32_t q0 = (uint32_t)qw[(size_t)kk0 * NDIM + n];
                uint32_t q1 = (uint32_t)qw[(size_t)(kk0 + 1) * NDIM + n];
                float s = sc[(size_t)g * NDIM + n];
                int zw = qz[g * (NDIM / 8) + (n >> 3)];
                float z = (float)((zw >> ((n & 7) << 2)) & 15);
                float w00 = ((float)((q0 >> sh) & 15) - z) * s;
                float w01 = ((float)((q0 >> (sh + 4)) & 15) - z) * s;
                float w10 = ((float)((q1 >> sh) & 15) - z) * s;
                float w11 = ((float)((q1 >> (sh + 4)) & 15) - z) * s;
                r[2 * h]     = pack_h2(w00, w01);   // reg0 (k 0-7)
                r[2 * h + 1] = pack_h2(w10, w11);   // reg1 (k 8-15)
            }
            ov[j].x = r[0]; ov[j].y = r[1]; ov[j].z = r[2]; ov[j].w = r[3];
        }
        uint4* dst = g_Wfrag + ((size_t)n64 * K16 + k16) * 128 + l;
#pragma unroll
        for (int j = 0; j < 4; ++j) dst[j * 32] = ov[j];
    }
}

// ---------------------------------------------------------------------------
// Main GEMM: C = A @ W^T + bias + residual.  NO shared memory, NO barriers.
// Both operands LDG'd directly in mma fragment layout; register ping-pong
// with 1 k16-step prefetch distance. 8 warps (4m x 2n), warp tile 32x64.
// ---------------------------------------------------------------------------
__global__ void __launch_bounds__(256, 2)
k_gemm(const float* __restrict__ residual, const float* __restrict__ bias,
       float* __restrict__ out) {
    const int tid  = threadIdx.x;
    const int wid  = tid >> 5;
    const int lane = tid & 31;
    const int warp_m = wid & 3;   // 4 warps along M (32 rows)
    const int warp_n = wid >> 2;  // 2 warps along N (64 cols)

    // L2-friendly raster: supertiles of 8 m-tiles x 32 n-tiles
    const int bid = blockIdx.x;
    const int tm_ = ((bid >> 8) << 3) | (bid & 7);
    const int tn_ = (bid >> 3) & 31;

    const int m16idx0 = tm_ * 8 + warp_m * 2;        // mt=0 tile row
    const int n64idx  = tn_ * 2 + warp_n;

    const uint4* pA0 = g_Afrag + (size_t)m16idx0 * K16 * 32 + lane;
    const uint4* pA1 = pA0 + (size_t)K16 * 32;       // mt=1
    const uint4* pB  = g_Wfrag + (size_t)n64idx * K16 * 128 + lane;

    float acc[2][8][4];
#pragma unroll
    for (int mt = 0; mt < 2; ++mt)
#pragma unroll
        for (int f = 0; f < 8; ++f)
#pragma unroll
            for (int j = 0; j < 4; ++j) acc[mt][f][j] = 0.f;

#define LOAD_STEP(Av, Bv, s_)                                                  \
    do {                                                                       \
        Bv[0] = __ldg(pB + (size_t)(s_)*128);                                  \
        Bv[1] = __ldg(pB + (size_t)(s_)*128 + 32);                             \
        Bv[2] = __ldg(pB + (size_t)(s_)*128 + 64);                             \
        Bv[3] = __ldg(pB + (size_t)(s_)*128 + 96);                             \
        Av[0] = __ldg(pA0 + (size_t)(s_)*32);                                  \
        Av[1] = __ldg(pA1 + (size_t)(s_)*32);                                  \
    } while (0)

#define MMA_STEP(Av, Bv)                                                       \
    do {                                                                       \
        _Pragma("unroll")                                                      \
        for (int mt = 0; mt < 2; ++mt) {                                       \
            const uint32_t* ar = (const uint32_t*)&Av[mt];                     \
            _Pragma("unroll")                                                  \
            for (int f = 0; f < 8; ++f) {                                      \
                const uint32_t* br =                                           \
                    (const uint32_t*)&Bv[f >> 1] + ((f & 1) << 1);             \
                mma16816(acc[mt][f], ar, br);                                  \
            }                                                                  \
        }                                                                      \
    } while (0)

    uint4 Av0[2], Bv0[4], Av1[2], Bv1[4];
    LOAD_STEP(Av0, Bv0, 0);

#pragma unroll 1
    for (int s = 0; s < K16; s += 2) {
        LOAD_STEP(Av1, Bv1, s + 1);
        MMA_STEP(Av0, Bv0);
        if (s + 2 < K16) LOAD_STEP(Av0, Bv0, s + 2);
        MMA_STEP(Av1, Bv1);
    }

    // Epilogue: fp32 acc + bias + residual -> out
    const int r  = lane >> 2;
    const int c2 = (lane & 3) * 2;
    const int mbase = tm_ * TM + warp_m * 32;
    const int nbase = tn_ * TN + warp_n * 64;
#pragma unroll
    for (int mt = 0; mt < 2; ++mt) {
#pragma unroll
        for (int half = 0; half < 2; ++half) {   // rows r and r+8
            const size_t m = (size_t)(mbase + mt * 16 + r + half * 8);
            const float* rp = residual + m * NDIM + nbase;
            float* op = out + m * NDIM + nbase;
#pragma unroll
            for (int f = 0; f < 8; ++f) {
                const int n = f * 8 + c2;
                float2 res = *(const float2*)(rp + n);
                float2 bz  = *(const float2*)(bias + nbase + n);
                float2 o;
                o.x = acc[mt][f][2 * half]     + bz.x + res.x;
                o.y = acc[mt][f][2 * half + 1] + bz.y + res.y;
                *(float2*)(op + n) = o;
            }
        }
    }
}

// ---------------------------------------------------------------------------
extern "C" void kernel_launch(void* const* d_in, const int* in_sizes, int n_in,
                              void* d_out, int out_size) {
    const float* input    = (const float*)d_in[0];   // [2,4096,4096] f32
    const float* residual = (const float*)d_in[1];   // [2,4096,4096] f32
    const int*   qweight  = (const int*)d_in[2];     // [512,4096] i32
    const float* scales   = (const float*)d_in[3];   // [32,4096] f32
    const int*   qzeros   = (const int*)d_in[4];     // [32,512] i32
    const float* bias     = (const float*)d_in[5];   // [4096] f32
    float* out = (float*)d_out;

    k_pre<<<ACONV_BLOCKS + DEQ_BLOCKS, 256>>>(input, qweight, scales, qzeros);

    const int nblocks = (MDIM / TM) * (NDIM / TN);   // 2048
    k_gemm<<<nblocks, 256>>>(residual, bias, out);
}

// round 10
// speedup vs baseline: 1.0132x; 1.0132x over previous
#include <cuda_runtime.h>
#include <cuda_fp16.h>
#include <cstdint>

// Problem dims
#define MDIM 8192   // B*S
#define NDIM 4096
#define KDIM 4096
#define K16  (KDIM / 16)     // 256 k16 tiles

// GEMM tiling: 128x128 CTA, 8 warps (4m x 2n), warp tile 32x64
#define TM 128
#define TN 128

// Pre-pass grid split (256-thread blocks, 8 warps each)
#define ACONV_BLOCKS ((MDIM / 16) * K16 / 8)        // 16384
#define DEQ_BLOCKS   ((NDIM / 64) * K16 / 8)        // 2048

// Fragment-layout scratch (allocation-free rule: __device__ globals).
// Padded by one block so the branch-free mainloop may prefetch one step
// past the end (values unused).
// A: per (m16, k16) tile: 512B block, lane l owns bytes [16l, 16l+16) = a0..a3
__device__ uint4 g_Afrag[(MDIM / 16) * (size_t)K16 * 32 + 64];
// W: per (n64, k16) block: 2KB; j in 0..3 selects frag pair (2j, 2j+1)
__device__ uint4 g_Wfrag[(NDIM / 64) * (size_t)K16 * 128 + 256];

// ---------------------------------------------------------------------------
__device__ __forceinline__ void mma16816(float* d, const uint32_t* a,
                                         const uint32_t* b) {
    asm volatile(
        "mma.sync.aligned.m16n8k16.row.col.f32.f16.f16.f32 "
        "{%0,%1,%2,%3}, {%4,%5,%6,%7}, {%8,%9}, {%0,%1,%2,%3};"
        : "+f"(d[0]), "+f"(d[1]), "+f"(d[2]), "+f"(d[3])
        : "r"(a[0]), "r"(a[1]), "r"(a[2]), "r"(a[3]), "r"(b[0]), "r"(b[1]));
}

__device__ __forceinline__ uint32_t pack_h2(float x, float y) {
    __half2 h = __floats2half2_rn(x, y);
    return *(uint32_t*)&h;
}

// ---------------------------------------------------------------------------
// Merged pre-pass (unchanged semantics from R9).
// ---------------------------------------------------------------------------
__global__ void __launch_bounds__(256)
k_pre(const float* __restrict__ in, const int* __restrict__ qw,
      const float* __restrict__ sc, const int* __restrict__ qz) {
    const int l = threadIdx.x & 31;
    if (blockIdx.x < ACONV_BLOCKS) {
        int w = (blockIdx.x << 3) | (threadIdx.x >> 5);
        int k16 = w & (K16 - 1);
        int m16 = w >> 8;
        int m = (m16 << 4) + (l >> 2);
        int k = (k16 << 4) + 2 * (l & 3);
        const float* p = in + (size_t)m * KDIM + k;
        float2 f0 = *(const float2*)(p);
        float2 f1 = *(const float2*)(p + 8 * KDIM);
        float2 f2 = *(const float2*)(p + 8);
        float2 f3 = *(const float2*)(p + 8 * KDIM + 8);
        uint4 o;
        o.x = pack_h2(f0.x, f0.y);
        o.y = pack_h2(f1.x, f1.y);
        o.z = pack_h2(f2.x, f2.y);
        o.w = pack_h2(f3.x, f3.y);
        g_Afrag[((size_t)m16 * K16 + k16) * 32 + l] = o;
    } else {
        int w = ((blockIdx.x - ACONV_BLOCKS) << 3) | (threadIdx.x >> 5);
        int k16 = w & (K16 - 1);
        int n64 = w >> 8;                 // 0..63
        int nb = n64 << 6;
        int g   = k16 >> 3;               // group = k/128
        int kk0 = k16 << 1;               // q row for k 0..7 of this tile
        int sh  = (l & 3) << 3;           // nibble-pair start bit
        uint4 ov[4];
#pragma unroll
        for (int j = 0; j < 4; ++j) {
            uint32_t r[4];
#pragma unroll
            for (int h = 0; h < 2; ++h) {
                int f = 2 * j + h;
                int n = nb + f * 8 + (l >> 2);
                uint32_t q0 = (uint32_t)qw[(size_t)kk0 * NDIM + n];
                uint32_t q1 = (uint32_t)qw[(size_t)(kk0 + 1) * NDIM + n];
                float s = sc[(size_t)g * NDIM + n];
                int zw = qz[g * (NDIM / 8) + (n >> 3)];
                float z = (float)((zw >> ((n & 7) << 2)) & 15);
                float w00 = ((float)((q0 >> sh) & 15) - z) * s;
                float w01 = ((float)((q0 >> (sh + 4)) & 15) - z) * s;
                float w10 = ((float)((q1 >> sh) & 15) - z) * s;
                float w11 = ((float)((q1 >> (sh + 4)) & 15) - z) * s;
                r[2 * h]     = pack_h2(w00, w01);   // reg0 (k 0-7)
                r[2 * h + 1] = pack_h2(w10, w11);   // reg1 (k 8-15)
            }
            ov[j].x = r[0]; ov[j].y = r[1]; ov[j].z = r[2]; ov[j].w = r[3];
        }
        uint4* dst = g_Wfrag + ((size_t)n64 * K16 + k16) * 128 + l;
#pragma unroll
        for (int j = 0; j < 4; ++j) dst[j * 32] = ov[j];
    }
}

// ---------------------------------------------------------------------------
// Main GEMM: C = A @ W^T + bias + residual.  No smem, no barriers.
// Register ping-pong, A loads issued a full step early (cold in L1),
// B loads interleaved between MMA f-groups (warm in L1 via 4x dup +
// sibling CTA sharing). Pointer-increment addressing, branch-free loop.
// ---------------------------------------------------------------------------
__global__ void __launch_bounds__(256, 2)
k_gemm(const float* __restrict__ residual, const float* __restrict__ bias,
       float* __restrict__ out) {
    const int tid  = threadIdx.x;
    const int wid  = tid >> 5;
    const int lane = tid & 31;
    const int warp_m = wid & 3;   // 4 warps along M (32 rows)
    const int warp_n = wid >> 2;  // 2 warps along N (64 cols)

    // L2-friendly raster: supertiles of 8 m-tiles x 32 n-tiles.
    // Adjacent bids share tn_ -> co-resident CTAs share the whole B panel.
    const int bid = blockIdx.x;
    const int tm_ = ((bid >> 8) << 3) | (bid & 7);
    const int tn_ = (bid >> 3) & 31;

    const int m16idx0 = tm_ * 8 + warp_m * 2;        // mt=0 tile row
    const int n64idx  = tn_ * 2 + warp_n;

    const uint4* pA0 = g_Afrag + (size_t)m16idx0 * K16 * 32 + lane;
    const uint4* pA1 = pA0 + (size_t)K16 * 32;       // mt=1
    const uint4* pB  = g_Wfrag + (size_t)n64idx * K16 * 128 + lane;

    float acc[2][8][4];
#pragma unroll
    for (int mt = 0; mt < 2; ++mt)
#pragma unroll
        for (int f = 0; f < 8; ++f)
#pragma unroll
            for (int j = 0; j < 4; ++j) acc[mt][f][j] = 0.f;

    // MMA group: one mt, f-range [f0, f0+4)
#define MMA_G(mt, f0, Av, Bv)                                                  \
    do {                                                                       \
        const uint32_t* ar = (const uint32_t*)&(Av)[mt];                       \
        _Pragma("unroll")                                                      \
        for (int f = (f0); f < (f0) + 4; ++f) {                                \
            const uint32_t* br =                                               \
                (const uint32_t*)&(Bv)[f >> 1] + ((f & 1) << 1);               \
            mma16816(acc[mt][f], ar, br);                                      \
        }                                                                      \
    } while (0)

    uint4 Av0[2], Bv0[4], Av1[2], Bv1[4];
    // Preload step 0 (A first: cold), and A of step 1 early.
    Av0[0] = __ldg(pA0);
    Av0[1] = __ldg(pA1);
    Bv0[0] = __ldg(pB);
    Bv0[1] = __ldg(pB + 32);
    Bv0[2] = __ldg(pB + 64);
    Bv0[3] = __ldg(pB + 96);

#pragma unroll 1
    for (int it = 0; it < K16 / 2; ++it) {
        // ---- step s (even): uses Av0/Bv0 ----
        // A for s+1: issue first (L1-cold, longest latency)
        Av1[0] = __ldg(pA0 + 32);
        Av1[1] = __ldg(pA1 + 32);
        MMA_G(0, 0, Av0, Bv0);
        Bv1[0] = __ldg(pB + 128);
        Bv1[1] = __ldg(pB + 160);
        MMA_G(0, 4, Av0, Bv0);
        Bv1[2] = __ldg(pB + 192);
        Bv1[3] = __ldg(pB + 224);
        MMA_G(1, 0, Av0, Bv0);
        MMA_G(1, 4, Av0, Bv0);

        // ---- step s+1 (odd): uses Av1/Bv1; prefetch s+2 ----
        Av0[0] = __ldg(pA0 + 64);
        Av0[1] = __ldg(pA1 + 64);
        MMA_G(0, 0, Av1, Bv1);
        Bv0[0] = __ldg(pB + 256);
        Bv0[1] = __ldg(pB + 288);
        MMA_G(0, 4, Av1, Bv1);
        Bv0[2] = __ldg(pB + 320);
        Bv0[3] = __ldg(pB + 352);
        MMA_G(1, 0, Av1, Bv1);
        MMA_G(1, 4, Av1, Bv1);

        pA0 += 64;
        pA1 += 64;
        pB += 256;
    }

    // Epilogue: fp32 acc + bias + residual -> out
    const int r  = lane >> 2;
    const int c2 = (lane & 3) * 2;
    const int mbase = tm_ * TM + warp_m * 32;
    const int nbase = tn_ * TN + warp_n * 64;
#pragma unroll
    for (int mt = 0; mt < 2; ++mt) {
#pragma unroll
        for (int half = 0; half < 2; ++half) {   // rows r and r+8
            const size_t m = (size_t)(mbase + mt * 16 + r + half * 8);
            const float* rp = residual + m * NDIM + nbase;
            float* op = out + m * NDIM + nbase;
#pragma unroll
            for (int f = 0; f < 8; ++f) {
                const int n = f * 8 + c2;
                float2 res = *(const float2*)(rp + n);
                float2 bz  = *(const float2*)(bias + nbase + n);
                float2 o;
                o.x = acc[mt][f][2 * half]     + bz.x + res.x;
                o.y = acc[mt][f][2 * half + 1] + bz.y + res.y;
                *(float2*)(op + n) = o;
            }
        }
    }
}

// ---------------------------------------------------------------------------
extern "C" void kernel_launch(void* const* d_in, const int* in_sizes, int n_in,
                              void* d_out, int out_size) {
    const float* input    = (const float*)d_in[0];   // [2,4096,4096] f32
    const float* residual = (const float*)d_in[1];   // [2,4096,4096] f32
    const int*   qweight  = (const int*)d_in[2];     // [512,4096] i32
    const float* scales   = (const float*)d_in[3];   // [32,4096] f32
    const int*   qzeros   = (const int*)d_in[4];     // [32,512] i32
    const float* bias     = (const float*)d_in[5];   // [4096] f32
    float* out = (float*)d_out;

    k_pre<<<ACONV_BLOCKS + DEQ_BLOCKS, 256>>>(input, qweight, scales, qzeros);

    const int nblocks = (MDIM / TM) * (NDIM / TN);   // 2048
    k_gemm<<<nblocks, 256>>>(residual, bias, out);
}